// round 8
// baseline (speedup 1.0000x reference)
#include <cuda_runtime.h>
#include <cstddef>

// SpecialFlatten == batched float2 transpose: in2 [B, R, CP] -> out2 [B, CP, R]
// B=32, R=2048, C=512, CP=256.
//
// v10 = v9 (software-pipelined double buffer, 32Rx32CP stages, NT=4) with ONE
// change: __launch_bounds__(256, 8) to force regs<=32 and restore 8 CTAs/SM
// (v9's 40 regs capped residency at 6 CTAs/SM -> occ 68.8%).

namespace {
constexpr int B   = 32;
constexpr int R   = 2048;
constexpr int CP  = 256;           // float2 columns
constexpr int C4  = CP / 2;        // 128 float4 per input row
constexpr int R4  = R / 2;         // 1024 float4 per output row
constexpr int TILE_R = 32;         // float2 rows per stage (16 pairs)
constexpr int TILE_C = 32;         // float2 cols per tile (= 16 float4)
constexpr int NT  = 4;             // stages per CTA (covers 128 rows)
}

__global__ __launch_bounds__(256, 8)
void special_flatten_v10(const float4* __restrict__ in,
                         float4* __restrict__ out) {
    __shared__ float2 sA[2][16][33];   // even rows (row 2m -> sA[buf][m])
    __shared__ float2 sB[2][16][33];   // odd rows

    const int b = blockIdx.z;
    const float4* __restrict__ inb  = in  + (size_t)b * R * C4;
    float4* __restrict__       outb = out + (size_t)b * CP * R4;

    const int tid = threadIdx.x;
    const int tx  = tid & 15;          // float4 col within tile (0..15)
    const int ty  = tid >> 4;          // row pair (0..15)
    const int ctile  = blockIdx.x;
    const int c4     = ctile * (TILE_C / 2) + tx;
    const int r0base = blockIdx.y * (TILE_R * NT);

    // ---- Prologue: load stage 0 into buffer 0 ----
    {
        const float4 v0 = inb[(size_t)(r0base + 2 * ty    ) * C4 + c4];
        const float4 v1 = inb[(size_t)(r0base + 2 * ty + 1) * C4 + c4];
        sA[0][ty][tx]      = make_float2(v0.x, v0.y);
        sA[0][ty][tx + 16] = make_float2(v0.z, v0.w);
        sB[0][ty][tx]      = make_float2(v1.x, v1.y);
        sB[0][ty][tx + 16] = make_float2(v1.z, v1.w);
    }
    __syncthreads();

#pragma unroll
    for (int t = 0; t < NT; t++) {
        // ---- Prefetch stage t+1 (LDG issued before store phase) ----
        float4 w0, w1;
        if (t + 1 < NT) {
            const int r0 = r0base + (t + 1) * TILE_R;
            w0 = inb[(size_t)(r0 + 2 * ty    ) * C4 + c4];
            w1 = inb[(size_t)(r0 + 2 * ty + 1) * C4 + c4];
        }

        // ---- Store stage t from buf[t&1]: LDS.64 lane-linear, 2x STG.128 ----
        {
            const int cur = t & 1;
            const int sx  = tid & 15;          // float4 R-index in stage (0..15)
            const int sy  = tid >> 4;          // 0..15
            const int r4  = (r0base + t * TILE_R) / 2 + sx;
#pragma unroll
            for (int n = 0; n < 2; n++) {
                const int c  = sy + 16 * n;    // CP-local col 0..31
                const int sc = (c >> 1) + (c & 1) * 16;
                const float2 a  = sA[cur][sx][sc];   // in2[2*sx][c]
                const float2 bb = sB[cur][sx][sc];   // in2[2*sx+1][c]
                outb[(size_t)(ctile * TILE_C + c) * R4 + r4] =
                    make_float4(a.x, a.y, bb.x, bb.y);
            }
        }

        // ---- Commit prefetch into the other buffer ----
        if (t + 1 < NT) {
            const int nxt = (t + 1) & 1;
            sA[nxt][ty][tx]      = make_float2(w0.x, w0.y);
            sA[nxt][ty][tx + 16] = make_float2(w0.z, w0.w);
            sB[nxt][ty][tx]      = make_float2(w1.x, w1.y);
            sB[nxt][ty][tx + 16] = make_float2(w1.z, w1.w);
            __syncthreads();
        }
    }
}

extern "C" void kernel_launch(void* const* d_in, const int* in_sizes, int n_in,
                              void* d_out, int out_size) {
    const float4* in  = (const float4*)d_in[0];
    float4*       out = (float4*)d_out;

    dim3 block(256, 1, 1);
    dim3 grid(CP / TILE_C, R / (TILE_R * NT), B);   // (8, 16, 32) = 4096 blocks
    special_flatten_v10<<<grid, block>>>(in, out);
}

// round 9
// speedup vs baseline: 1.0567x; 1.0567x over previous
#include <cuda_runtime.h>
#include <cstddef>
#include <cstdint>

// SpecialFlatten == batched float2 transpose: in2 [B, R, CP] -> out2 [B, CP, R]
// B=32, R=2048, C=512, CP=256.
//
// v11: cp.async (LDGSTS) double-buffered pipeline — v9's read/write overlap
// WITHOUT register-held prefetch. Stage = 32 input rows x 16 float4 cols.
// Raw float4 smem rows [32][17] with XOR swizzle pcol = col ^ ((row>>1)&7):
// store-phase LDS.128 of row pairs is bank-group bijective (0 conflicts),
// each thread emits two output float4 (c=2j, 2j+1). NT=4 stages per CTA.

namespace {
constexpr int B   = 32;
constexpr int R   = 2048;
constexpr int CP  = 256;           // float2 columns
constexpr int C4  = CP / 2;        // 128 float4 per input row
constexpr int R4  = R / 2;         // 1024 float4 per output row
constexpr int NT  = 4;             // stages per CTA (covers 128 rows)
}

__global__ __launch_bounds__(256)
void special_flatten_v11(const float4* __restrict__ in,
                         float4* __restrict__ out) {
    __shared__ float4 s[2][32][17];    // 17408 B, row stride 272 B

    const int b = blockIdx.z;
    const float4* __restrict__ inb  = in  + (size_t)b * R * C4;
    float4* __restrict__       outb = out + (size_t)b * CP * R4;

    const int tid = threadIdx.x;
    const int tx  = tid & 15;          // load: float4 col (0..15)
    const int ty  = tid >> 4;          // load: row (0..15), also row+16
    const int ctile  = blockIdx.x;
    const int c4     = ctile * 16 + tx;
    const int r0base = blockIdx.y * (32 * NT);

    // swizzled dst columns for this thread's two rows (same for r and r+16)
    const int pc_ld = tx ^ ((ty >> 1) & 7);

    // store-phase indices
    const int m  = tid & 15;           // output r4 offset within stage (0..15)
    const int j  = tid >> 4;           // input float4 col (0..15)
    const int pc_st = j ^ (m & 7);     // swizzled col for rows 2m, 2m+1

    // ---- issue stage 0 ----
    {
        uint32_t d0 = (uint32_t)__cvta_generic_to_shared(&s[0][ty][pc_ld]);
        uint32_t d1 = (uint32_t)__cvta_generic_to_shared(&s[0][ty + 16][pc_ld]);
        const float4* s0 = &inb[(size_t)(r0base + ty) * C4 + c4];
        const float4* s1 = &inb[(size_t)(r0base + ty + 16) * C4 + c4];
        asm volatile("cp.async.cg.shared.global [%0], [%1], 16;\n" :: "r"(d0), "l"(s0));
        asm volatile("cp.async.cg.shared.global [%0], [%1], 16;\n" :: "r"(d1), "l"(s1));
        asm volatile("cp.async.commit_group;\n" ::: "memory");
    }

#pragma unroll
    for (int t = 0; t < NT; t++) {
        // ---- issue stage t+1 into the other buffer ----
        if (t + 1 < NT) {
            const int buf = (t + 1) & 1;
            const int r0  = r0base + (t + 1) * 32;
            uint32_t d0 = (uint32_t)__cvta_generic_to_shared(&s[buf][ty][pc_ld]);
            uint32_t d1 = (uint32_t)__cvta_generic_to_shared(&s[buf][ty + 16][pc_ld]);
            const float4* s0 = &inb[(size_t)(r0 + ty) * C4 + c4];
            const float4* s1 = &inb[(size_t)(r0 + ty + 16) * C4 + c4];
            asm volatile("cp.async.cg.shared.global [%0], [%1], 16;\n" :: "r"(d0), "l"(s0));
            asm volatile("cp.async.cg.shared.global [%0], [%1], 16;\n" :: "r"(d1), "l"(s1));
            asm volatile("cp.async.commit_group;\n" ::: "memory");
            asm volatile("cp.async.wait_group 1;\n" ::: "memory");
        } else {
            asm volatile("cp.async.wait_group 0;\n" ::: "memory");
        }
        __syncthreads();

        // ---- store stage t: 2x LDS.128 (conflict-free) -> 2x STG.128 ----
        {
            const int cur = t & 1;
            const float4 a4 = s[cur][2 * m][pc_st];       // in2 row 2m, cols 2j,2j+1
            const float4 b4 = s[cur][2 * m + 1][pc_st];   // in2 row 2m+1
            const size_t r4 = (size_t)(r0base / 2) + t * 16 + m;
            outb[(size_t)(ctile * 32 + 2 * j) * R4 + r4] =
                make_float4(a4.x, a4.y, b4.x, b4.y);
            outb[(size_t)(ctile * 32 + 2 * j + 1) * R4 + r4] =
                make_float4(a4.z, a4.w, b4.z, b4.w);
        }

        // protect buf[(t+2)&1] (== buf[t&1]) before next iteration's issue
        if (t + 1 < NT) __syncthreads();
    }
}

extern "C" void kernel_launch(void* const* d_in, const int* in_sizes, int n_in,
                              void* d_out, int out_size) {
    const float4* in  = (const float4*)d_in[0];
    float4*       out = (float4*)d_out;

    dim3 block(256, 1, 1);
    dim3 grid(CP / 32, R / (32 * NT), B);   // (8, 16, 32) = 4096 blocks
    special_flatten_v11<<<grid, block>>>(in, out);
}